// round 8
// baseline (speedup 1.0000x reference)
#include <cuda_runtime.h>
#include <math.h>

// CurveGraphic2d: 16 cubic Beziers -> 16 x 256x256 canvases.
// canvas = clip(1 - (min_d/w + eps)^aa, 0, 1); w <= 8 so any pixel with
// min_d >= w outputs exactly 0 -> tile/warp culling is exact.
//
// Two-kernel structure: per-curve sample points + per-tile cull flags are
// computed ONCE (kernel A, 16 blocks), then the per-pixel kernel (B) has a
// near-zero prelude: culled blocks do 1 uniform LDG + 1 STG and exit.

#define CANVAS_H 256
#define CANVAS_W 256
#define NSAMP 32
#define MAX_LEN 300.0f
#define EPS 1e-6f

__device__ float2        g_samples[16][NSAMP];   // (y, x) per sample
__device__ unsigned char g_skip[16 * 256];       // 1 = tile produces all zeros

// ---------------- Kernel A: samples + tile cull flags (grid=16) -------------
__global__ __launch_bounds__(256)
void curve_setup_kernel(const float* __restrict__ inputs,   // [16,4,2]
                        const float* __restrict__ widths)   // [16]
{
    __shared__ float4 ssamp[NSAMP / 2];

    const int b   = blockIdx.x;
    const int tid = threadIdx.x;

    if (tid < 32) {
        const int s = tid;
        float cy[4], cx[4];
#pragma unroll
        for (int i = 0; i < 4; i++) {
            cy[i] = inputs[(b * 4 + i) * 2 + 0] * (float)CANVAS_H;
            cx[i] = inputs[(b * 4 + i) * 2 + 1] * (float)CANVAS_W;
        }

        const float t = (float)s / 31.0f;           // linspace(0,1,32)
        const float u = 1.0f - t;
        const float B0 = u * u * u;
        const float B1 = 3.0f * t * u * u;
        const float B2 = 3.0f * t * t * u;
        const float B3 = t * t * t;

        // Full-curve sample (arc length)
        const float py = B0 * cy[0] + B1 * cy[1] + B2 * cy[2] + B3 * cy[3];
        const float px = B0 * cx[0] + B1 * cx[1] + B2 * cx[2] + B3 * cx[3];

        const float pym = __shfl_up_sync(0xffffffffu, py, 1);
        const float pxm = __shfl_up_sync(0xffffffffu, px, 1);
        const float dyy = py - pym;
        const float dxx = px - pxm;
        float seg = (s > 0) ? sqrtf(dyy * dyy + dxx * dxx) : 0.0f;
#pragma unroll
        for (int off = 16; off; off >>= 1)
            seg += __shfl_xor_sync(0xffffffffu, seg, off);
        const float arc = seg;

        const float tt = fminf(1.0f, MAX_LEN / (arc + EPS));
        const float ut = 1.0f - tt;

        // de Casteljau left subdivision at tt
        const float b0y = ut * cy[0] + tt * cy[1], b0x = ut * cx[0] + tt * cx[1];
        const float b1y = ut * cy[1] + tt * cy[2], b1x = ut * cx[1] + tt * cx[2];
        const float b2y = ut * cy[2] + tt * cy[3], b2x = ut * cx[2] + tt * cx[3];
        const float c0y = ut * b0y + tt * b1y,     c0x = ut * b0x + tt * b1x;
        const float c1y = ut * b1y + tt * b2y,     c1x = ut * b1x + tt * b2x;
        const float d0y = ut * c0y + tt * c1y,     d0x = ut * c0x + tt * c1x;

        // Truncated-curve sample
        const float sy = B0 * cy[0] + B1 * b0y + B2 * c0y + B3 * d0y;
        const float sx = B0 * cx[0] + B1 * b0x + B2 * c0x + B3 * d0x;

        ((float2*)ssamp)[s] = make_float2(sy, sx);
        g_samples[b][s]     = make_float2(sy, sx);
    }
    __syncthreads();

    // Each thread culls one 16x16 tile of canvas b.
    const int tile = tid;
    const float tcy = (float)((tile >> 4) << 4) + 7.5f;
    const float tcx = (float)((tile & 15) << 4) + 7.5f;
    float m = 3.4e38f;
#pragma unroll
    for (int k = 0; k < NSAMP / 2; k++) {
        const float4 v = ssamp[k];
        const float dy0 = tcy - v.x;
        const float dx0 = tcx - v.y;
        m = fminf(m, fmaf(dy0, dy0, dx0 * dx0));
        const float dy1 = tcy - v.z;
        const float dx1 = tcx - v.w;
        m = fminf(m, fmaf(dy1, dy1, dx1 * dx1));
    }
    // Tile half-diagonal 8*sqrt(2)=11.3137 + 1 px fp-safety margin.
    const float thr = widths[b] + 11.3137085f + 1.0f;
    g_skip[(b << 8) | tile] = (m >= thr * thr) ? 1 : 0;
}

// ---------------- Kernel B: per-pixel rendering (grid=(256,16)) -------------
__global__ __launch_bounds__(256)
void curve_render_kernel(const float* __restrict__ widths,  // [16]
                         const float* __restrict__ aafac,   // [16]
                         float* __restrict__ out)           // [16,256,256]
{
    const int b    = blockIdx.y;
    const int tile = blockIdx.x;
    const int ty0  = (tile >> 4) << 4;
    const int tx0  = (tile & 15) << 4;
    const int tid  = threadIdx.x;

    const int lx = tid & 15;
    const int ly = tid >> 4;
    const int py = ty0 + ly;
    const int px = tx0 + lx;
    float* const optr = out + (((b << 8) + py) << 8) + px;

    // Uniform flag load: one sector per warp, L2/L1-resident.
    if (__ldg(&g_skip[(b << 8) | tile])) { *optr = 0.0f; return; }

    // Warp cull: each warp covers a 2x16 strip (rows ly&~1 .. +1).
    {
        const int lane = tid & 31;
        const float2 sp = __ldg(&g_samples[b][lane]);
        const float wcy = (float)(ty0 + (ly & ~1)) + 0.5f;
        const float wcx = (float)tx0 + 7.5f;
        const float ddy = wcy - sp.x;
        const float ddx = wcx - sp.y;
        float d2 = ddy * ddy + ddx * ddx;
#pragma unroll
        for (int off = 16; off; off >>= 1)
            d2 = fminf(d2, __shfl_xor_sync(0xffffffffu, d2, off));
        // Strip half-diagonal sqrt(7.5^2+0.5^2)=7.5166 + 0.5 margin.
        const float thr = widths[b] + 7.517f + 0.5f;
        if (d2 >= thr * thr) { *optr = 0.0f; return; }   // warp-uniform
    }

    // Full evaluation: min squared distance over 32 samples.
    // Uniform-address LDG.128 x16, fully unrolled -> high MLP, L1 broadcast.
    const float4* __restrict__ gs = (const float4*)g_samples[b];
    const float fy = (float)py;
    const float fx = (float)px;
    float m = 3.4e38f;
#pragma unroll
    for (int k = 0; k < NSAMP / 2; k++) {
        const float4 v = __ldg(&gs[k]);   // (y0,x0,y1,x1)
        const float dy0 = fy - v.x;
        const float dx0 = fx - v.y;
        m = fminf(m, fmaf(dy0, dy0, dx0 * dx0));
        const float dy1 = fy - v.z;
        const float dx1 = fx - v.w;
        m = fminf(m, fmaf(dy1, dy1, dx1 * dx1));
    }

    const float md   = sqrtf(m);
    const float base = md / widths[b] + EPS;
    const float val  = 1.0f - __powf(base, aafac[b]);
    *optr = fminf(fmaxf(val, 0.0f), 1.0f);
}

extern "C" void kernel_launch(void* const* d_in, const int* in_sizes, int n_in,
                              void* d_out, int out_size)
{
    const float* inputs = (const float*)d_in[0];   // [16,4,2]
    const float* widths = (const float*)d_in[1];   // [16]
    const float* aafac  = (const float*)d_in[2];   // [16]
    float* out = (float*)d_out;                    // [16,256,256]

    curve_setup_kernel<<<16, 256>>>(inputs, widths);
    dim3 grid(256, 16);
    curve_render_kernel<<<grid, 256>>>(widths, aafac, out);
}